// round 16
// baseline (speedup 1.0000x reference)
#include <cuda_runtime.h>
#include <cuda_fp16.h>
#include <cstdint>
#include <cstddef>

#define C_SEQ   2304
#define C_DIM   2048
#define C_ROWS  4608
#define C_FFN   8192
#define C_SCALE 0.08838834764831845f   // 1/sqrt(128)

// ----------------------------------------------------------------- scratch
__device__ float g_t1[6144];
__device__ float g_t2[6144];
__device__ __half g_nrm[(size_t)C_ROWS * C_DIM];
__device__ __half g_qH[(size_t)C_ROWS * C_DIM];
__device__ __half g_kH[(size_t)C_ROWS * C_DIM];
__device__ __half g_vH[(size_t)C_ROWS * C_DIM];
__device__ __half g_aoH[(size_t)C_ROWS * C_DIM];
__device__ __half g_mid[(size_t)C_ROWS * C_FFN];
// transposed fp16 weights: [N, K]
__device__ __half g_wq[(size_t)C_DIM * C_DIM];
__device__ __half g_wk[(size_t)C_DIM * C_DIM];
__device__ __half g_wv[(size_t)C_DIM * C_DIM];
__device__ __half g_wo[(size_t)C_DIM * C_DIM];
__device__ __half g_f1[(size_t)C_FFN * C_DIM];
__device__ __half g_f2[(size_t)C_DIM * C_FFN];

// ----------------------------------------------------------------- helpers
__device__ __forceinline__ uint32_t smem_u32(const void* p) {
    uint32_t a;
    asm("{ .reg .u64 t; cvta.to.shared.u64 t, %1; cvt.u32.u64 %0, t; }" : "=r"(a) : "l"(p));
    return a;
}
#define CP16(dst, src) \
    asm volatile("cp.async.cg.shared.global [%0], [%1], 16;" :: "r"(dst), "l"(src) : "memory")
#define CP_COMMIT() asm volatile("cp.async.commit_group;" ::: "memory")
#define CP_WAIT1()  asm volatile("cp.async.wait_group 1;" ::: "memory")
#define LDSM4(r, p) \
    asm volatile("ldmatrix.sync.aligned.m8n8.x4.shared.b16 {%0,%1,%2,%3}, [%4];" \
        : "=r"((r)[0]), "=r"((r)[1]), "=r"((r)[2]), "=r"((r)[3]) : "r"(p))
#define LDSM4T(r, p) \
    asm volatile("ldmatrix.sync.aligned.m8n8.x4.trans.shared.b16 {%0,%1,%2,%3}, [%4];" \
        : "=r"((r)[0]), "=r"((r)[1]), "=r"((r)[2]), "=r"((r)[3]) : "r"(p))

__device__ __forceinline__ void mma_f16(float* d, const uint32_t* a, const uint32_t* b) {
    asm volatile("mma.sync.aligned.m16n8k16.row.col.f32.f16.f16.f32 "
        "{%0,%1,%2,%3}, {%4,%5,%6,%7}, {%8,%9}, {%0,%1,%2,%3};"
        : "+f"(d[0]), "+f"(d[1]), "+f"(d[2]), "+f"(d[3])
        : "r"(a[0]), "r"(a[1]), "r"(a[2]), "r"(a[3]), "r"(b[0]), "r"(b[1]));
}
__device__ __forceinline__ float gelu_t(float x) {
    float u2 = 1.5957691216057308f * (x + 0.044715f * x * x * x);
    return __fdividef(x, 1.f + __expf(-u2));
}

// ----------------------------------------------------------------- temb -> t1/t2
__global__ __launch_bounds__(256) void temb_kernel(
    const float* __restrict__ temb,
    const float* __restrict__ lw1, const float* __restrict__ lb1,
    const float* __restrict__ lw2, const float* __restrict__ lb2,
    float* __restrict__ t1, float* __restrict__ t2)
{
    __shared__ float s[512];
    int tid = threadIdx.x;
    float a = temb[tid], b = temb[tid + 256];
    s[tid]       = a / (1.f + __expf(-a));
    s[tid + 256] = b / (1.f + __expf(-b));
    __syncthreads();
    const float* lw = blockIdx.y ? lw2 : lw1;
    const float* lb = blockIdx.y ? lb2 : lb1;
    float* t        = blockIdx.y ? t2  : t1;
    int j = blockIdx.x * 256 + tid;
    float acc = lb[j];
#pragma unroll 8
    for (int i = 0; i < 512; ++i) acc += s[i] * lw[(size_t)i * 6144 + j];
    t[j] = acc;
}

// ----------------------------------------------------------------- LN store helper
__device__ __forceinline__ void ln_store(
    const float* xv, float mu, float rstd, const float* __restrict__ t,
    const float* __restrict__ nw, const float* __restrict__ nb,
    __half* __restrict__ H, size_t ob, int tid)
{
#pragma unroll
    for (int e = 0; e < 8; e += 2) {
        int c = tid * 8 + e;
        float a0 = ((xv[e]   - mu) * rstd * nw[c]   + nb[c])   * (1.f + t[2048 + c])   + t[c];
        float a1 = ((xv[e+1] - mu) * rstd * nw[c+1] + nb[c+1]) * (1.f + t[2048 + c+1]) + t[c+1];
        __half2 hp; hp.x = __float2half(a0); hp.y = __float2half(a1);
        *(__half2*)(H + ob + e) = hp;
    }
}

__device__ __forceinline__ void ln_body(
    const float* xv, const float* __restrict__ t,
    const float* __restrict__ nw, const float* __restrict__ nb,
    __half* __restrict__ H, size_t ob, int tid)
{
    float s = 0.f, ss = 0.f;
#pragma unroll
    for (int e = 0; e < 8; ++e) { s += xv[e]; ss += xv[e] * xv[e]; }
#pragma unroll
    for (int o = 16; o > 0; o >>= 1) {
        s  += __shfl_xor_sync(0xffffffffu, s, o);
        ss += __shfl_xor_sync(0xffffffffu, ss, o);
    }
    __shared__ float rs[8], rss[8];
    if ((tid & 31) == 0) { rs[tid >> 5] = s; rss[tid >> 5] = ss; }
    __syncthreads();
    float tot = 0.f, tot2 = 0.f;
#pragma unroll
    for (int w = 0; w < 8; ++w) { tot += rs[w]; tot2 += rss[w]; }
    float mu   = tot * (1.f / 2048.f);
    float var  = tot2 * (1.f / 2048.f) - mu * mu;
    float rstd = rsqrtf(var + 1e-5f);
    ln_store(xv, mu, rstd, t, nw, nb, H, ob, tid);
}

// ----------------------------------------------------------------- first LN: reads inputs, writes st + nrm
__global__ __launch_bounds__(256) void ln_mod_first(
    const float* __restrict__ src0, const float* __restrict__ src1,
    const float* __restrict__ t,
    const float* __restrict__ nw, const float* __restrict__ nb,
    __half* __restrict__ H, float* __restrict__ st)
{
    int row = blockIdx.x, tid = threadIdx.x;
    const float* x = (row < C_SEQ) ? src0 + (size_t)row * C_DIM
                                   : src1 + (size_t)(row - C_SEQ) * C_DIM;
    float4 v0 = *(const float4*)(x + tid * 8);
    float4 v1 = *(const float4*)(x + tid * 8 + 4);
    size_t base = (size_t)row * C_DIM + tid * 8;
    *(float4*)&st[base]     = v0;
    *(float4*)&st[base + 4] = v1;
    float xv[8] = {v0.x, v0.y, v0.z, v0.w, v1.x, v1.y, v1.z, v1.w};
    ln_body(xv, t, nw, nb, H, base, tid);
}

// ----------------------------------------------------------------- plain LN on st
__global__ __launch_bounds__(256) void ln_mod_kernel(
    const float* __restrict__ st, const float* __restrict__ t,
    const float* __restrict__ nw, const float* __restrict__ nb,
    __half* __restrict__ H)
{
    int row = blockIdx.x, tid = threadIdx.x;
    size_t base = (size_t)row * C_DIM + tid * 8;
    float4 v0 = *(const float4*)&st[base];
    float4 v1 = *(const float4*)&st[base + 4];
    float xv[8] = {v0.x, v0.y, v0.z, v0.w, v1.x, v1.y, v1.z, v1.w};
    ln_body(xv, t, nw, nb, H, base, tid);
}

// ----------------------------------------------------------------- weight transpose -> fp16
__global__ __launch_bounds__(256) void wconv_kernel(
    const float* __restrict__ W, __half* __restrict__ T, int K, int N)
{
    __shared__ float t[32][33];
    int n0 = blockIdx.x * 32, k0 = blockIdx.y * 32;
    int tx = threadIdx.x & 31, ty = threadIdx.x >> 5;
#pragma unroll
    for (int i = 0; i < 4; ++i)
        t[ty * 4 + i][tx] = W[(size_t)(k0 + ty * 4 + i) * N + n0 + tx];
    __syncthreads();
#pragma unroll
    for (int i = 0; i < 4; ++i) {
        int r = ty * 4 + i;
        T[(size_t)(n0 + r) * K + k0 + tx] = __float2half(t[tx][r]);
    }
}

// ----------------------------------------------------------------- mma.sync HGEMM (fp32 accum)
// 4 warps, 64x64 warp tiles. D[M,N] = A[M,K] * B[N,K]^T; BK=64, 3-stage.
// act: 1=gelu->fp16; 2=bias->fp16; 3=residual: stF[row,col] += gate[col]*(acc+bias)
#define MG_TILE_B  18432            // 128 rows * 72 halves * 2B
#define MG_STAGE_B (2 * MG_TILE_B)
#define MG_SMEM    (3 * MG_STAGE_B) // 110592

__global__ __launch_bounds__(128) void mma_gemm(
    const __half* __restrict__ A, const __half* __restrict__ B,
    const float* __restrict__ bias, const float* __restrict__ gate,
    float* __restrict__ stF, __half* __restrict__ outH,
    int N, int K, int act)
{
    extern __shared__ char smc[];
    const uint32_t sb = smem_u32(smc);
    const int tid = threadIdx.x, lane = tid & 31, wid = tid >> 5;
    const int wm = wid & 1, wn = wid >> 1;
    const int m0 = blockIdx.y << 7, n0 = blockIdx.x << 7;

    auto load_chunk = [&](int c, int buf) {
        int k0 = c << 6;
        uint32_t st = sb + buf * MG_STAGE_B;
#pragma unroll
        for (int j = 0; j < 8; ++j) {
            int q = tid + j * 128;
            int r = q >> 3, c8 = q & 7;
            uint32_t d = st + r * 144 + c8 * 16;
            CP16(d,             A + (size_t)(m0 + r) * K + k0 + c8 * 8);
            CP16(d + MG_TILE_B, B + (size_t)(n0 + r) * K + k0 + c8 * 8);
        }
    };

    const int mrow = (lane & 7) + ((lane >> 3) & 1) * 8;
    const int achk = lane >> 4;
    const int nrow = (lane & 7) + (lane >> 4) * 8;
    const int bchk = (lane >> 3) & 1;
    const uint32_t aoff = (uint32_t)(wm * 64 + mrow) * 144 + achk * 16;
    const uint32_t boff = (uint32_t)(wn * 64 + nrow) * 144 + bchk * 16;

    float acc[4][8][4];
#pragma unroll
    for (int i = 0; i < 4; ++i)
#pragma unroll
        for (int j = 0; j < 8; ++j)
#pragma unroll
            for (int e = 0; e < 4; ++e) acc[i][j][e] = 0.f;

    const int NC = K >> 6;
    load_chunk(0, 0); CP_COMMIT();
    load_chunk(1, 1); CP_COMMIT();

    int buf = 0, pbuf = 2;
    for (int c = 0; c < NC; ++c) {
        CP_WAIT1();
        __syncthreads();
        uint32_t st = sb + buf * MG_STAGE_B;
#pragma unroll
        for (int ks = 0; ks < 4; ++ks) {
            uint32_t ah[4][4], bh[4][4];
#pragma unroll
            for (int mt = 0; mt < 4; ++mt)
                LDSM4(ah[mt], st + aoff + mt * (16 * 144) + ks * 32);
#pragma unroll
            for (int g = 0; g < 4; ++g)
                LDSM4(bh[g], st + MG_TILE_B + boff + g * (16 * 144) + ks * 32);
#pragma unroll
            for (int mt = 0; mt < 4; ++mt)
#pragma unroll
                for (int g = 0; g < 4; ++g)
#pragma unroll
                    for (int h = 0; h < 2; ++h)
                        mma_f16(acc[mt][g * 2 + h], ah[mt], &bh[g][h * 2]);
        }
        if (c + 2 < NC) load_chunk(c + 2, pbuf);
        CP_COMMIT();
        buf  = (buf  == 2) ? 0 : buf  + 1;
        pbuf = (pbuf == 2) ? 0 : pbuf + 1;
    }

    const int g = lane >> 2, t4 = lane & 3;
#pragma unroll
    for (int mt = 0; mt < 4; ++mt) {
#pragma unroll
        for (int nt = 0; nt < 8; ++nt) {
            float* a = acc[mt][nt];
            int row = m0 + wm * 64 + mt * 16 + g;
            int col = n0 + wn * 64 + nt * 8 + 2 * t4;
            float b0 = bias[col], b1 = bias[col + 1];
            float v0 = a[0] + b0, v1 = a[1] + b1;
            float v2 = a[2] + b0, v3 = a[3] + b1;
            if (act == 3) {
                float g0v = gate[col], g1v = gate[col + 1];
                float2 s0 = *(float2*)(stF + (size_t)row * N + col);
                float2 s1 = *(float2*)(stF + (size_t)(row + 8) * N + col);
                s0.x += g0v * v0; s0.y += g1v * v1;
                s1.x += g0v * v2; s1.y += g1v * v3;
                *(float2*)(stF + (size_t)row * N + col)       = s0;
                *(float2*)(stF + (size_t)(row + 8) * N + col) = s1;
            } else {
                if (act == 1) { v0 = gelu_t(v0); v1 = gelu_t(v1); v2 = gelu_t(v2); v3 = gelu_t(v3); }
                __half2 p;
                p.x = __float2half(v0); p.y = __float2half(v1);
                *(__half2*)(outH + (size_t)row * N + col) = p;
                p.x = __float2half(v2); p.y = __float2half(v3);
                *(__half2*)(outH + (size_t)(row + 8) * N + col) = p;
            }
        }
    }
}

// ----------------------------------------------------------------- RMSNorm + RoPE in-place fp16
__global__ __launch_bounds__(256) void rmsrope_kernel(
    __half* __restrict__ Qm, __half* __restrict__ Km,
    const float* __restrict__ nq, const float* __restrict__ nk,
    const float* __restrict__ cos_h, const float* __restrict__ sin_h,
    const float* __restrict__ cos_r, const float* __restrict__ sin_r)
{
    int row = blockIdx.x, tid = threadIdx.x;
    int isk = blockIdx.y;
    __half* x = (isk ? Km : Qm) + (size_t)row * C_DIM;
    const float* nw = isk ? nk : nq;
    float oscale = isk ? 1.f : C_SCALE;
    int isr = row >= C_SEQ;
    int pos = isr ? row - C_SEQ : row;
    const float* cp = (isr ? cos_r : cos_h) + (size_t)pos * 128;
    const float* sp = (isr ? sin_r : sin_h) + (size_t)pos * 128;
    float4 raw = *(const float4*)(x + tid * 8);
    __half2* hp2 = (__half2*)&raw;
    float xv[8];
#pragma unroll
    for (int p = 0; p < 4; ++p) {
        float2 f = __half22float2(hp2[p]);
        xv[2 * p] = f.x; xv[2 * p + 1] = f.y;
    }
    float ss = 0.f;
#pragma unroll
    for (int e = 0; e < 8; ++e) ss += xv[e] * xv[e];
#pragma unroll
    for (int o = 16; o > 0; o >>= 1) ss += __shfl_xor_sync(0xffffffffu, ss, o);
    __shared__ float rss[8];
    if ((tid & 31) == 0) rss[tid >> 5] = ss;
    __syncthreads();
    float tot = 0.f;
#pragma unroll
    for (int w = 0; w < 8; ++w) tot += rss[w];
    float rstd = rsqrtf(tot * (1.f / 2048.f) + 1e-6f);
    float4 outr;
    __half2* op2 = (__half2*)&outr;
#pragma unroll
    for (int p = 0; p < 4; ++p) {
        int ce = tid * 8 + 2 * p;
        int de = ce & 127;
        float x1 = xv[2 * p]     * rstd * nw[ce];
        float x2 = xv[2 * p + 1] * rstd * nw[ce + 1];
        float cv = cp[de], sv = sp[de + 1];
        __half2 hp;
        hp.x = __float2half((x1 * cv - x2 * sv) * oscale);
        hp.y = __float2half((x1 * sv + x2 * cv) * oscale);
        op2[p] = hp;
    }
    *(float4*)(x + tid * 8) = outr;
}

// ----------------------------------------------------------------- attention (fp16 mma flash, register softmax)
__device__ __forceinline__ int combined_row(int fi, int j) {
    int hi = j / 48;
    int wi = j - hi * 48;
    int base = (wi < 24) ? 0 : C_SEQ;
    int ww   = (wi < 24) ? wi : wi - 24;
    return base + fi * 576 + hi * 24 + ww;
}

#define AQ_STR 136
#define AP_STR 72
#define A_TILE  17408                 // 64*136*2 bytes
#define AO_Q    0
#define AO_K(b) (17408 + (b) * A_TILE)
#define AO_V(b) (52224 + (b) * A_TILE)
#define AO_PH   87040                 // fp16 [64][72]
#define AO_PMAX 96256                 // fp32 [2][64]
#define AO_PSUM 96768                 // fp32 [2][64]
#define AO_M    97280
#define AO_LR   97536
#define ATTN_SMEM 97792

__global__ __launch_bounds__(256) void attn_kernel(
    const __half* __restrict__ QhG, const __half* __restrict__ KhG,
    const __half* __restrict__ VhG, __half* __restrict__ OH)
{
    extern __shared__ char smc[];
    const uint32_t sb = smem_u32(smc);
    float* pmax = (float*)(smc + AO_PMAX);
    float* psum = (float*)(smc + AO_PSUM);
    float* mrow = (float*)(smc + AO_M);
    float* lrow = (float*)(smc + AO_LR);

    const int tid  = threadIdx.x, lane = tid & 31, wid = tid >> 5;
    const int wm = wid & 3, wn = wid >> 2;
    const int fi = blockIdx.y >> 4;
    const int coloff = (blockIdx.y & 15) * 128;
    const int q0 = blockIdx.x * 64;
    const int t4 = lane & 3;
    const int r1 = wm * 16 + (lane >> 2), r2 = r1 + 8;

    const int mrow_a = (lane & 7) + ((lane >> 3) & 1) * 8;
    const int achk   = lane >> 4;
    const int nrow_b = (lane & 7) + (lane >> 4) * 8;
    const int bchk   = (lane >> 3) & 1;
    const int vrow   = mrow_a;
    const int vc8    = (lane >> 4) * 8;

#pragma unroll
    for (int i = 0; i < 4; ++i) {
        int c = tid + i * 256;
        int r = c >> 4, ch8 = (c & 15) * 8;
        int grow = combined_row(fi, q0 + r);
        uint32_t d = (uint32_t)(r * AQ_STR + ch8) * 2;
        CP16(sb + AO_Q + d, QhG + (size_t)grow * C_DIM + coloff + ch8);
    }
    auto load_kv = [&](int kc, int buf) {
        int k0 = kc * 64;
#pragma unroll
        for (int i = 0; i < 4; ++i) {
            int c = tid + i * 256;
            int r = c >> 4, ch8 = (c & 15) * 8;
            int grow = combined_row(fi, k0 + r);
            size_t g = (size_t)grow * C_DIM + coloff + ch8;
            uint32_t d = (uint32_t)(r * AQ_STR + ch8) * 2;
            CP16(sb + AO_K(buf) + d, KhG + g);
            CP16(sb + AO_V(buf) + d, VhG + g);
        }
    };
    load_kv(0, 0);
    CP_COMMIT();
    if (tid < 64) { mrow[tid] = -1e30f; lrow[tid] = 0.f; }

    float oacc[8][4];
#pragma unroll
    for (int f = 0; f < 8; ++f)
#pragma unroll
        for (int e = 0; e < 4; ++e) oacc[f][e] = 0.f;

    const uint32_t qoff = (uint32_t)((wm * 16 + mrow_a) * AQ_STR + achk * 8) * 2;
    const uint32_t poff = (uint32_t)((wm * 16 + mrow_a) * AP_STR + achk * 8) * 2;

    for (int kc = 0; kc < 18; ++kc) {
        if (kc + 1 < 18) load_kv(kc + 1, (kc + 1) & 1);
        CP_COMMIT();
        CP_WAIT1();
        __syncthreads();                          // B1: KV visible
        const int buf = kc & 1;
        const uint32_t kb = sb + AO_K(buf), vb = sb + AO_V(buf);

        float sacc[4][4];
#pragma unroll
        for (int f = 0; f < 4; ++f)
#pragma unroll
            for (int e = 0; e < 4; ++e) sacc[f][e] = 0.f;
        const uint32_t koff = (uint32_t)((wn * 32 + nrow_b) * AQ_STR + bchk * 8) * 2;
#pragma unroll
        for (int ks = 0; ks < 8; ++ks) {
            uint32_t ah[4];
            LDSM4(ah, sb + AO_Q + qoff + ks * 32);
#pragma unroll
            for (int g2 = 0; g2 < 2; ++g2) {
                uint32_t bh[4];
                LDSM4(bh, kb + koff + g2 * (16 * AQ_STR * 2) + ks * 32);
#pragma unroll
                for (int h = 0; h < 2; ++h)
                    mma_f16(sacc[g2 * 2 + h], ah, &bh[h * 2]);
            }
        }

        float m1 = -1e30f, m2 = -1e30f;
#pragma unroll
        for (int f = 0; f < 4; ++f) {
            m1 = fmaxf(m1, fmaxf(sacc[f][0], sacc[f][1]));
            m2 = fmaxf(m2, fmaxf(sacc[f][2], sacc[f][3]));
        }
        m1 = fmaxf(m1, __shfl_xor_sync(0xffffffffu, m1, 1));
        m1 = fmaxf(m1, __shfl_xor_sync(0xffffffffu, m1, 2));
        m2 = fmaxf(m2, __shfl_xor_sync(0xffffffffu, m2, 1));
        m2 = fmaxf(m2, __shfl_xor_sync(0xffffffffu, m2, 2));
        if (t4 == 0) { pmax[wn * 64 + r1] = m1; pmax[wn * 64 + r2] = m2; }
        __syncthreads();                          // B2: pmax ready

        float mo1 = mrow[r1], mo2 = mrow[r2];
        float mx1 = fmaxf(mo1, fmaxf(pmax[r1], pmax[64 + r1]));
        float mx2 = fmaxf(mo2, fmaxf(pmax[r2], pmax[64 + r2]));
        float fac1 = __expf(mo1 - mx1), fac2 = __expf(mo2 - mx2);
        float s1 = 0.f, s2 = 0.f;
        __half* PH = (__half*)(smc + AO_PH);
#pragma unroll
        for (int f = 0; f < 4; ++f) {
            int cc = wn * 32 + f * 8 + 2 * t4;
            float e0 = __expf(sacc[f][0] - mx1), e1 = __expf(sacc[f][1] - mx1);
            float e2 = __expf(sacc[f][2] - mx2), e3 = __expf(sacc[f][3] - mx2);
            s1 += e0 + e1; s2 += e2 + e3;
            __half2 hp;
            hp.x = __float2half(e0); hp.y = __float2half(e1);
            *(__half2*)(PH + r1 * AP_STR + cc) = hp;
            hp.x = __float2half(e2); hp.y = __float2half(e3);
            *(__half2*)(PH + r2 * AP_STR + cc) = hp;
        }
        s1 += __shfl_xor_sync(0xffffffffu, s1, 1);
        s1 += __shfl_xor_sync(0xffffffffu, s1, 2);
        s2 += __shfl_xor_sync(0xffffffffu, s2, 1);
        s2 += __shfl_xor_sync(0xffffffffu, s2, 2);
        if (t4 == 0) { psum[wn * 64 + r1] = s1; psum[wn * 64 + r2] = s2; }
#pragma unroll
        for (int f = 0; f < 8; ++f) {
            oacc[f][0] *= fac1; oacc[f][1] *= fac1;
            oacc[f][2] *= fac2; oacc[f][3] *= fac2;
        }
        __syncthreads();                          // B3: PH + psum visible
        if (wn == 0 && t4 == 0) {
            lrow[r1] = lrow[r1] * fac1 + psum[r1] + psum[64 + r1];
            mrow[r1] = mx1;
            lrow[r2] = lrow[r2] * fac2 + psum[r2] + psum[64 + r2];
            mrow[r2] = mx2;
        }

#pragma unroll
        for (int ks = 0; ks < 4; ++ks) {
            uint32_t ph[4];
            LDSM4(ph, sb + AO_PH + poff + ks * 32);
#pragma unroll
            for (int g2 = 0; g2 < 4; ++g2) {
                uint32_t vh[4];
                uint32_t p = (uint32_t)((ks * 16 + vrow) * AQ_STR + wn * 64 + g2 * 16 + vc8) * 2;
                LDSM4T(vh, vb + p);
#pragma unroll
                for (int h = 0; h < 2; ++h)
                    mma_f16(oacc[g2 * 2 + h], ph, &vh[h * 2]);
            }
        }
        __syncthreads();                          // B4
    }

    {
        float i1 = 1.f / lrow[r1], i2 = 1.f / lrow[r2];
        int g1 = combined_row(fi, q0 + r1), g2r = combined_row(fi, q0 + r2);
#pragma unroll
        for (int f = 0; f < 8; ++f) {
            int col = coloff + wn * 64 + f * 8 + 2 * t4;
            __half2 p;
            p.x = __float2half(oacc[f][0] * i1); p.y = __float2half(oacc[f][1] * i1);
            *(__half2*)(OH + (size_t)g1 * C_DIM + col) = p;
            p.x = __float2half(oacc[f][2] * i2); p.y = __float2half(oacc[f][3] * i2);
            *(__half2*)(OH + (size_t)g2r * C_DIM + col) = p;
        }
    }
}

// ----------------------------------------------------------------- launch
extern "C" void kernel_launch(void* const* d_in, const int* in_sizes, int n_in,
                              void* d_out, int out_size)
{
    const float* temb  = (const float*)d_in[2];
    const float* cos_h = (const float*)d_in[3];
    const float* sin_h = (const float*)d_in[4];
    const float* cos_r = (const float*)d_in[5];
    const float* sin_r = (const float*)d_in[6];
    const float* l1lw = (const float*)d_in[7],  *l1lb = (const float*)d_in[8];
    const float* l1nw = (const float*)d_in[9],  *l1nb = (const float*)d_in[10];
    const float* l2lw = (const float*)d_in[11], *l2lb = (const float*)d_in[12];
    const float* l2nw = (const float*)d_in[13], *l2nb = (const float*)d_in[14];
    const float* wq = (const float*)d_in[15], *bq = (const float*)d_in[16];
    const float* wk = (const float*)d_in[17], *bk = (const float*)d_in[18];
    const float* wv = (const float*)d_in[19], *bv = (const float*)d_in[20];
    const float* nqw = (const float*)d_in[21], *nkw = (const float*)d_in[22];
    const float* wo = (const float*)d_in[23], *bo = (const float*)d_in[24];
    const float* fw1 = (const float*)d_in[25], *fb1 = (const float*)d_in[26];
    const float* fw2 = (const float*)d_in[27], *fb2 = (const float*)d_in[28];
    float* st = (float*)d_out;

    float *t1, *t2;
    __half *nrm, *qH, *kH, *vH, *aoH, *mid;
    __half *wqh, *wkh, *wvh, *woh, *f1h, *f2h;
    cudaGetSymbolAddress((void**)&t1,  g_t1);
    cudaGetSymbolAddress((void**)&t2,  g_t2);
    cudaGetSymbolAddress((void**)&nrm, g_nrm);
    cudaGetSymbolAddress((void**)&qH, g_qH);
    cudaGetSymbolAddress((void**)&kH, g_kH);
    cudaGetSymbolAddress((void**)&vH, g_vH);
    cudaGetSymbolAddress((void**)&aoH, g_aoH);
    cudaGetSymbolAddress((void**)&mid, g_mid);
    cudaGetSymbolAddress((void**)&wqh, g_wq);
    cudaGetSymbolAddress((void**)&wkh, g_wk);
    cudaGetSymbolAddress((void**)&wvh, g_wv);
    cudaGetSymbolAddress((void**)&woh, g_wo);
    cudaGetSymbolAddress((void**)&f1h, g_f1);
    cudaGetSymbolAddress((void**)&f2h, g_f2);

    cudaFuncSetAttribute(attn_kernel, cudaFuncAttributeMaxDynamicSharedMemorySize, ATTN_SMEM);
    cudaFuncSetAttribute(mma_gemm,    cudaFuncAttributeMaxDynamicSharedMemorySize, MG_SMEM);

    wconv_kernel<<<dim3(64, 64),   256>>>(wq,  wqh, C_DIM, C_DIM);
    wconv_kernel<<<dim3(64, 64),   256>>>(wk,  wkh, C_DIM, C_DIM);
    wconv_kernel<<<dim3(64, 64),   256>>>(wv,  wvh, C_DIM, C_DIM);
    wconv_kernel<<<dim3(64, 64),   256>>>(wo,  woh, C_DIM, C_DIM);
    wconv_kernel<<<dim3(256, 64),  256>>>(fw1, f1h, C_DIM, C_FFN);
    wconv_kernel<<<dim3(64, 256),  256>>>(fw2, f2h, C_FFN, C_DIM);

    temb_kernel<<<dim3(24, 2), 256>>>(temb, l1lw, l1lb, l2lw, l2lb, t1, t2);
    ln_mod_first<<<C_ROWS, 256>>>((const float*)d_in[0], (const float*)d_in[1],
                                  t1, l1nw, l1nb, nrm, st);
    mma_gemm<<<dim3(16, 36), 128, MG_SMEM>>>(nrm, wqh, bq, bq, 0, qH, C_DIM, C_DIM, 2);
    mma_gemm<<<dim3(16, 36), 128, MG_SMEM>>>(nrm, wkh, bk, bk, 0, kH, C_DIM, C_DIM, 2);
    mma_gemm<<<dim3(16, 36), 128, MG_SMEM>>>(nrm, wvh, bv, bv, 0, vH, C_DIM, C_DIM, 2);
    rmsrope_kernel<<<dim3(C_ROWS, 2), 256>>>(qH, kH, nqw, nkw, cos_h, sin_h, cos_r, sin_r);
    attn_kernel<<<dim3(18, 64), 256, ATTN_SMEM>>>(qH, kH, vH, aoH);
    mma_gemm<<<dim3(16, 36), 128, MG_SMEM>>>(aoH, woh, bo, t1 + 4096, st, 0, C_DIM, C_DIM, 3);
    ln_mod_kernel<<<C_ROWS, 256>>>(st, t2, l2nw, l2nb, nrm);
    mma_gemm<<<dim3(64, 36), 128, MG_SMEM>>>(nrm, f1h, fb1, fb1, 0, mid, C_FFN, C_DIM, 1);
    mma_gemm<<<dim3(16, 36), 128, MG_SMEM>>>(mid, f2h, fb2, t2 + 4096, st, 0, C_DIM, C_FFN, 3);
}

// round 17
// speedup vs baseline: 1.6898x; 1.6898x over previous
#include <cuda_runtime.h>
#include <cuda_fp16.h>
#include <cstdint>
#include <cstddef>

#define C_SEQ   2304
#define C_DIM   2048
#define C_ROWS  4608
#define C_FFN   8192
#define C_SCALE 0.08838834764831845f   // 1/sqrt(128)

// ----------------------------------------------------------------- scratch
__device__ float g_t1[6144];
__device__ float g_t2[6144];
__device__ __half g_nrm[(size_t)C_ROWS * C_DIM];
__device__ __half g_qH[(size_t)C_ROWS * C_DIM];
__device__ __half g_kH[(size_t)C_ROWS * C_DIM];
__device__ __half g_vH[(size_t)C_ROWS * C_DIM];
__device__ __half g_aoH[(size_t)C_ROWS * C_DIM];
__device__ __half g_mid[(size_t)C_ROWS * C_FFN];
// transposed fp16 weights: [N, K]
__device__ __half g_wq[(size_t)C_DIM * C_DIM];
__device__ __half g_wk[(size_t)C_DIM * C_DIM];
__device__ __half g_wv[(size_t)C_DIM * C_DIM];
__device__ __half g_wo[(size_t)C_DIM * C_DIM];
__device__ __half g_f1[(size_t)C_FFN * C_DIM];
__device__ __half g_f2[(size_t)C_DIM * C_FFN];

// ----------------------------------------------------------------- helpers
__device__ __forceinline__ uint32_t smem_u32(const void* p) {
    uint32_t a;
    asm("{ .reg .u64 t; cvta.to.shared.u64 t, %1; cvt.u32.u64 %0, t; }" : "=r"(a) : "l"(p));
    return a;
}
#define CP16(dst, src) \
    asm volatile("cp.async.cg.shared.global [%0], [%1], 16;" :: "r"(dst), "l"(src) : "memory")
#define CP_COMMIT() asm volatile("cp.async.commit_group;" ::: "memory")
#define CP_WAIT1()  asm volatile("cp.async.wait_group 1;" ::: "memory")
#define LDSM4(r, p) \
    asm volatile("ldmatrix.sync.aligned.m8n8.x4.shared.b16 {%0,%1,%2,%3}, [%4];" \
        : "=r"((r)[0]), "=r"((r)[1]), "=r"((r)[2]), "=r"((r)[3]) : "r"(p))
#define LDSM4T(r, p) \
    asm volatile("ldmatrix.sync.aligned.m8n8.x4.trans.shared.b16 {%0,%1,%2,%3}, [%4];" \
        : "=r"((r)[0]), "=r"((r)[1]), "=r"((r)[2]), "=r"((r)[3]) : "r"(p))

__device__ __forceinline__ void mma_f16(float* d, const uint32_t* a, const uint32_t* b) {
    asm volatile("mma.sync.aligned.m16n8k16.row.col.f32.f16.f16.f32 "
        "{%0,%1,%2,%3}, {%4,%5,%6,%7}, {%8,%9}, {%0,%1,%2,%3};"
        : "+f"(d[0]), "+f"(d[1]), "+f"(d[2]), "+f"(d[3])
        : "r"(a[0]), "r"(a[1]), "r"(a[2]), "r"(a[3]), "r"(b[0]), "r"(b[1]));
}
__device__ __forceinline__ float gelu_t(float x) {
    float u2 = 1.5957691216057308f * (x + 0.044715f * x * x * x);
    return __fdividef(x, 1.f + __expf(-u2));
}

// ----------------------------------------------------------------- temb -> t1/t2
__global__ __launch_bounds__(256) void temb_kernel(
    const float* __restrict__ temb,
    const float* __restrict__ lw1, const float* __restrict__ lb1,
    const float* __restrict__ lw2, const float* __restrict__ lb2,
    float* __restrict__ t1, float* __restrict__ t2)
{
    __shared__ float s[512];
    int tid = threadIdx.x;
    float a = temb[tid], b = temb[tid + 256];
    s[tid]       = a / (1.f + __expf(-a));
    s[tid + 256] = b / (1.f + __expf(-b));
    __syncthreads();
    const float* lw = blockIdx.y ? lw2 : lw1;
    const float* lb = blockIdx.y ? lb2 : lb1;
    float* t        = blockIdx.y ? t2  : t1;
    int j = blockIdx.x * 256 + tid;
    float acc = lb[j];
#pragma unroll 8
    for (int i = 0; i < 512; ++i) acc += s[i] * lw[(size_t)i * 6144 + j];
    t[j] = acc;
}

// ----------------------------------------------------------------- LN store helper
__device__ __forceinline__ void ln_store(
    const float* xv, float mu, float rstd, const float* __restrict__ t,
    const float* __restrict__ nw, const float* __restrict__ nb,
    __half* __restrict__ H, size_t ob, int tid)
{
#pragma unroll
    for (int e = 0; e < 8; e += 2) {
        int c = tid * 8 + e;
        float a0 = ((xv[e]   - mu) * rstd * nw[c]   + nb[c])   * (1.f + t[2048 + c])   + t[c];
        float a1 = ((xv[e+1] - mu) * rstd * nw[c+1] + nb[c+1]) * (1.f + t[2048 + c+1]) + t[c+1];
        __half2 hp; hp.x = __float2half(a0); hp.y = __float2half(a1);
        *(__half2*)(H + ob + e) = hp;
    }
}

__device__ __forceinline__ void ln_body(
    const float* xv, const float* __restrict__ t,
    const float* __restrict__ nw, const float* __restrict__ nb,
    __half* __restrict__ H, size_t ob, int tid)
{
    float s = 0.f, ss = 0.f;
#pragma unroll
    for (int e = 0; e < 8; ++e) { s += xv[e]; ss += xv[e] * xv[e]; }
#pragma unroll
    for (int o = 16; o > 0; o >>= 1) {
        s  += __shfl_xor_sync(0xffffffffu, s, o);
        ss += __shfl_xor_sync(0xffffffffu, ss, o);
    }
    __shared__ float rs[8], rss[8];
    if ((tid & 31) == 0) { rs[tid >> 5] = s; rss[tid >> 5] = ss; }
    __syncthreads();
    float tot = 0.f, tot2 = 0.f;
#pragma unroll
    for (int w = 0; w < 8; ++w) { tot += rs[w]; tot2 += rss[w]; }
    float mu   = tot * (1.f / 2048.f);
    float var  = tot2 * (1.f / 2048.f) - mu * mu;
    float rstd = rsqrtf(var + 1e-5f);
    ln_store(xv, mu, rstd, t, nw, nb, H, ob, tid);
}

// ----------------------------------------------------------------- first LN: reads inputs, writes st + nrm
__global__ __launch_bounds__(256) void ln_mod_first(
    const float* __restrict__ src0, const float* __restrict__ src1,
    const float* __restrict__ t,
    const float* __restrict__ nw, const float* __restrict__ nb,
    __half* __restrict__ H, float* __restrict__ st)
{
    int row = blockIdx.x, tid = threadIdx.x;
    const float* x = (row < C_SEQ) ? src0 + (size_t)row * C_DIM
                                   : src1 + (size_t)(row - C_SEQ) * C_DIM;
    float4 v0 = *(const float4*)(x + tid * 8);
    float4 v1 = *(const float4*)(x + tid * 8 + 4);
    size_t base = (size_t)row * C_DIM + tid * 8;
    *(float4*)&st[base]     = v0;
    *(float4*)&st[base + 4] = v1;
    float xv[8] = {v0.x, v0.y, v0.z, v0.w, v1.x, v1.y, v1.z, v1.w};
    ln_body(xv, t, nw, nb, H, base, tid);
}

// ----------------------------------------------------------------- plain LN on st
__global__ __launch_bounds__(256) void ln_mod_kernel(
    const float* __restrict__ st, const float* __restrict__ t,
    const float* __restrict__ nw, const float* __restrict__ nb,
    __half* __restrict__ H)
{
    int row = blockIdx.x, tid = threadIdx.x;
    size_t base = (size_t)row * C_DIM + tid * 8;
    float4 v0 = *(const float4*)&st[base];
    float4 v1 = *(const float4*)&st[base + 4];
    float xv[8] = {v0.x, v0.y, v0.z, v0.w, v1.x, v1.y, v1.z, v1.w};
    ln_body(xv, t, nw, nb, H, base, tid);
}

// ----------------------------------------------------------------- weight transpose -> fp16
__global__ __launch_bounds__(256) void wconv_kernel(
    const float* __restrict__ W, __half* __restrict__ T, int K, int N)
{
    __shared__ float t[32][33];
    int n0 = blockIdx.x * 32, k0 = blockIdx.y * 32;
    int tx = threadIdx.x & 31, ty = threadIdx.x >> 5;
#pragma unroll
    for (int i = 0; i < 4; ++i)
        t[ty * 4 + i][tx] = W[(size_t)(k0 + ty * 4 + i) * N + n0 + tx];
    __syncthreads();
#pragma unroll
    for (int i = 0; i < 4; ++i) {
        int r = ty * 4 + i;
        T[(size_t)(n0 + r) * K + k0 + tx] = __float2half(t[tx][r]);
    }
}

// ----------------------------------------------------------------- mma.sync HGEMM (fp32 accum)
// 8 warps, 32x64 warp tiles, 256 threads (R15 proven config). BK=64, 3-stage.
// act: 1=gelu->fp16; 2=bias->fp16; 3=residual: stF[row,col] += gate[col]*(acc+bias)
#define MG_TILE_B  18432            // 128 rows * 72 halves * 2B
#define MG_STAGE_B (2 * MG_TILE_B)
#define MG_SMEM    (3 * MG_STAGE_B) // 110592

__global__ __launch_bounds__(256) void mma_gemm(
    const __half* __restrict__ A, const __half* __restrict__ B,
    const float* __restrict__ bias, const float* __restrict__ gate,
    float* __restrict__ stF, __half* __restrict__ outH,
    int N, int K, int act)
{
    extern __shared__ char smc[];
    const uint32_t sb = smem_u32(smc);
    const int tid = threadIdx.x, lane = tid & 31, wid = tid >> 5;
    const int wm = wid & 3, wn = wid >> 2;
    const int m0 = blockIdx.y << 7, n0 = blockIdx.x << 7;

    auto load_chunk = [&](int c, int buf) {
        int k0 = c << 6;
        uint32_t st = sb + buf * MG_STAGE_B;
#pragma unroll
        for (int j = 0; j < 4; ++j) {
            int q = tid + j * 256;
            int r = q >> 3, c8 = q & 7;
            uint32_t d = st + r * 144 + c8 * 16;
            CP16(d,             A + (size_t)(m0 + r) * K + k0 + c8 * 8);
            CP16(d + MG_TILE_B, B + (size_t)(n0 + r) * K + k0 + c8 * 8);
        }
    };

    const int mrow = (lane & 7) + ((lane >> 3) & 1) * 8;
    const int achk = lane >> 4;
    const int nrow = (lane & 7) + (lane >> 4) * 8;
    const int bchk = (lane >> 3) & 1;
    const uint32_t aoff = (uint32_t)(wm * 32 + mrow) * 144 + achk * 16;
    const uint32_t boff = (uint32_t)(wn * 64 + nrow) * 144 + bchk * 16;

    float acc[2][8][4];
#pragma unroll
    for (int i = 0; i < 2; ++i)
#pragma unroll
        for (int j = 0; j < 8; ++j)
#pragma unroll
            for (int e = 0; e < 4; ++e) acc[i][j][e] = 0.f;

    const int NC = K >> 6;
    load_chunk(0, 0); CP_COMMIT();
    load_chunk(1, 1); CP_COMMIT();

    int buf = 0, pbuf = 2;
    for (int c = 0; c < NC; ++c) {
        CP_WAIT1();
        __syncthreads();
        uint32_t st = sb + buf * MG_STAGE_B;
#pragma unroll
        for (int ks = 0; ks < 4; ++ks) {
            uint32_t ah[2][4], bh[4][4];
#pragma unroll
            for (int mt = 0; mt < 2; ++mt)
                LDSM4(ah[mt], st + aoff + mt * (16 * 144) + ks * 32);
#pragma unroll
            for (int g = 0; g < 4; ++g)
                LDSM4(bh[g], st + MG_TILE_B + boff + g * (16 * 144) + ks * 32);
#pragma unroll
            for (int mt = 0; mt < 2; ++mt)
#pragma unroll
                for (int g = 0; g < 4; ++g)
#pragma unroll
                    for (int h = 0; h < 2; ++h)
                        mma_f16(acc[mt][g * 2 + h], ah[mt], &bh[g][h * 2]);
        }
        if (c + 2 < NC) load_chunk(c + 2, pbuf);
        CP_COMMIT();
        buf  = (buf  == 2) ? 0 : buf  + 1;
        pbuf = (pbuf == 2) ? 0 : pbuf + 1;
    }

    const int g = lane >> 2, t4 = lane & 3;
#pragma unroll
    for (int mt = 0; mt < 2; ++mt) {
#pragma unroll
        for (int nt = 0; nt < 8; ++nt) {
            float* a = acc[mt][nt];
            int row = m0 + wm * 32 + mt * 16 + g;
            int col = n0 + wn * 64 + nt * 8 + 2 * t4;
            float b0 = bias[col], b1 = bias[col + 1];
            float v0 = a[0] + b0, v1 = a[1] + b1;
            float v2 = a[2] + b0, v3 = a[3] + b1;
            if (act == 3) {
                float g0v = gate[col], g1v = gate[col + 1];
                float2 s0 = *(float2*)(stF + (size_t)row * N + col);
                float2 s1 = *(float2*)(stF + (size_t)(row + 8) * N + col);
                s0.x += g0v * v0; s0.y += g1v * v1;
                s1.x += g0v * v2; s1.y += g1v * v3;
                *(float2*)(stF + (size_t)row * N + col)       = s0;
                *(float2*)(stF + (size_t)(row + 8) * N + col) = s1;
            } else {
                if (act == 1) { v0 = gelu_t(v0); v1 = gelu_t(v1); v2 = gelu_t(v2); v3 = gelu_t(v3); }
                __half2 p;
                p.x = __float2half(v0); p.y = __float2half(v1);
                *(__half2*)(outH + (size_t)row * N + col) = p;
                p.x = __float2half(v2); p.y = __float2half(v3);
                *(__half2*)(outH + (size_t)(row + 8) * N + col) = p;
            }
        }
    }
}

// ----------------------------------------------------------------- RMSNorm + RoPE in-place fp16
__global__ __launch_bounds__(256) void rmsrope_kernel(
    __half* __restrict__ Qm, __half* __restrict__ Km,
    const float* __restrict__ nq, const float* __restrict__ nk,
    const float* __restrict__ cos_h, const float* __restrict__ sin_h,
    const float* __restrict__ cos_r, const float* __restrict__ sin_r)
{
    int row = blockIdx.x, tid = threadIdx.x;
    int isk = blockIdx.y;
    __half* x = (isk ? Km : Qm) + (size_t)row * C_DIM;
    const float* nw = isk ? nk : nq;
    float oscale = isk ? 1.f : C_SCALE;
    int isr = row >= C_SEQ;
    int pos = isr ? row - C_SEQ : row;
    const float* cp = (isr ? cos_r : cos_h) + (size_t)pos * 128;
    const float* sp = (isr ? sin_r : sin_h) + (size_t)pos * 128;
    float4 raw = *(const float4*)(x + tid * 8);
    __half2* hp2 = (__half2*)&raw;
    float xv[8];
#pragma unroll
    for (int p = 0; p < 4; ++p) {
        float2 f = __half22float2(hp2[p]);
        xv[2 * p] = f.x; xv[2 * p + 1] = f.y;
    }
    float ss = 0.f;
#pragma unroll
    for (int e = 0; e < 8; ++e) ss += xv[e] * xv[e];
#pragma unroll
    for (int o = 16; o > 0; o >>= 1) ss += __shfl_xor_sync(0xffffffffu, ss, o);
    __shared__ float rss[8];
    if ((tid & 31) == 0) rss[tid >> 5] = ss;
    __syncthreads();
    float tot = 0.f;
#pragma unroll
    for (int w = 0; w < 8; ++w) tot += rss[w];
    float rstd = rsqrtf(tot * (1.f / 2048.f) + 1e-6f);
    float4 outr;
    __half2* op2 = (__half2*)&outr;
#pragma unroll
    for (int p = 0; p < 4; ++p) {
        int ce = tid * 8 + 2 * p;
        int de = ce & 127;
        float x1 = xv[2 * p]     * rstd * nw[ce];
        float x2 = xv[2 * p + 1] * rstd * nw[ce + 1];
        float cv = cp[de], sv = sp[de + 1];
        __half2 hp;
        hp.x = __float2half((x1 * cv - x2 * sv) * oscale);
        hp.y = __float2half((x1 * sv + x2 * cv) * oscale);
        op2[p] = hp;
    }
    *(float4*)(x + tid * 8) = outr;
}

// ----------------------------------------------------------------- attention (fp16 mma flash, register softmax)
__device__ __forceinline__ int combined_row(int fi, int j) {
    int hi = j / 48;
    int wi = j - hi * 48;
    int base = (wi < 24) ? 0 : C_SEQ;
    int ww   = (wi < 24) ? wi : wi - 24;
    return base + fi * 576 + hi * 24 + ww;
}

#define AQ_STR 136
#define AP_STR 72
#define A_TILE  17408                 // 64*136*2 bytes
#define AO_Q    0
#define AO_K(b) (17408 + (b) * A_TILE)
#define AO_V(b) (52224 + (b) * A_TILE)
#define AO_PH   87040                 // fp16 [64][72]
#define AO_PMAX 96256                 // fp32 [2][64]
#define AO_PSUM 96768                 // fp32 [2][64]
#define AO_M    97280
#define AO_LR   97536
#define ATTN_SMEM 97792

__global__ __launch_bounds__(256) void attn_kernel(
    const __half* __restrict__ QhG, const __half* __restrict__ KhG,
    const __half* __restrict__ VhG, __half* __restrict__ OH)
{
    extern __shared__ char smc[];
    const uint32_t sb = smem_u32(smc);
    float* pmax = (float*)(smc + AO_PMAX);
    float* psum = (float*)(smc + AO_PSUM);
    float* mrow = (float*)(smc + AO_M);
    float* lrow = (float*)(smc + AO_LR);

    const int tid  = threadIdx.x, lane = tid & 31, wid = tid >> 5;
    const int wm = wid & 3, wn = wid >> 2;
    const int fi = blockIdx.y >> 4;
    const int coloff = (blockIdx.y & 15) * 128;
    const int q0 = blockIdx.x * 64;
    const int t4 = lane & 3;
    const int r1 = wm * 16 + (lane >> 2), r2 = r1 + 8;

    const int mrow_a = (lane & 7) + ((lane >> 3) & 1) * 8;
    const int achk   = lane >> 4;
    const int nrow_b = (lane & 7) + (lane >> 4) * 8;
    const int bchk   = (lane >> 3) & 1;
    const int vrow   = mrow_a;
    const int vc8    = (lane >> 4) * 8;

#pragma unroll
    for (int i = 0; i < 4; ++i) {
        int c = tid + i * 256;
        int r = c >> 4, ch8 = (c & 15) * 8;
        int grow = combined_row(fi, q0 + r);
        uint32_t d = (uint32_t)(r * AQ_STR + ch8) * 2;
        CP16(sb + AO_Q + d, QhG + (size_t)grow * C_DIM + coloff + ch8);
    }
    auto load_kv = [&](int kc, int buf) {
        int k0 = kc * 64;
#pragma unroll
        for (int i = 0; i < 4; ++i) {
            int c = tid + i * 256;
            int r = c >> 4, ch8 = (c & 15) * 8;
            int grow = combined_row(fi, k0 + r);
            size_t g = (size_t)grow * C_DIM + coloff + ch8;
            uint32_t d = (uint32_t)(r * AQ_STR + ch8) * 2;
            CP16(sb + AO_K(buf) + d, KhG + g);
            CP16(sb + AO_V(buf) + d, VhG + g);
        }
    };
    load_kv(0, 0);
    CP_COMMIT();
    if (tid < 64) { mrow[tid] = -1e30f; lrow[tid] = 0.f; }

    float oacc[8][4];
#pragma unroll
    for (int f = 0; f < 8; ++f)
#pragma unroll
        for (int e = 0; e < 4; ++e) oacc[f][e] = 0.f;

    const uint32_t qoff = (uint32_t)((wm * 16 + mrow_a) * AQ_STR + achk * 8) * 2;
    const uint32_t poff = (uint32_t)((wm * 16 + mrow_a) * AP_STR + achk * 8) * 2;

    for (int kc = 0; kc < 18; ++kc) {
        if (kc + 1 < 18) load_kv(kc + 1, (kc + 1) & 1);
        CP_COMMIT();
        CP_WAIT1();
        __syncthreads();                          // B1: KV visible
        const int buf = kc & 1;
        const uint32_t kb = sb + AO_K(buf), vb = sb + AO_V(buf);

        float sacc[4][4];
#pragma unroll
        for (int f = 0; f < 4; ++f)
#pragma unroll
            for (int e = 0; e < 4; ++e) sacc[f][e] = 0.f;
        const uint32_t koff = (uint32_t)((wn * 32 + nrow_b) * AQ_STR + bchk * 8) * 2;
#pragma unroll
        for (int ks = 0; ks < 8; ++ks) {
            uint32_t ah[4];
            LDSM4(ah, sb + AO_Q + qoff + ks * 32);
#pragma unroll
            for (int g2 = 0; g2 < 2; ++g2) {
                uint32_t bh[4];
                LDSM4(bh, kb + koff + g2 * (16 * AQ_STR * 2) + ks * 32);
#pragma unroll
                for (int h = 0; h < 2; ++h)
                    mma_f16(sacc[g2 * 2 + h], ah, &bh[h * 2]);
            }
        }

        float m1 = -1e30f, m2 = -1e30f;
#pragma unroll
        for (int f = 0; f < 4; ++f) {
            m1 = fmaxf(m1, fmaxf(sacc[f][0], sacc[f][1]));
            m2 = fmaxf(m2, fmaxf(sacc[f][2], sacc[f][3]));
        }
        m1 = fmaxf(m1, __shfl_xor_sync(0xffffffffu, m1, 1));
        m1 = fmaxf(m1, __shfl_xor_sync(0xffffffffu, m1, 2));
        m2 = fmaxf(m2, __shfl_xor_sync(0xffffffffu, m2, 1));
        m2 = fmaxf(m2, __shfl_xor_sync(0xffffffffu, m2, 2));
        if (t4 == 0) { pmax[wn * 64 + r1] = m1; pmax[wn * 64 + r2] = m2; }
        __syncthreads();                          // B2: pmax ready

        float mo1 = mrow[r1], mo2 = mrow[r2];
        float mx1 = fmaxf(mo1, fmaxf(pmax[r1], pmax[64 + r1]));
        float mx2 = fmaxf(mo2, fmaxf(pmax[r2], pmax[64 + r2]));
        float fac1 = __expf(mo1 - mx1), fac2 = __expf(mo2 - mx2);
        float s1 = 0.f, s2 = 0.f;
        __half* PH = (__half*)(smc + AO_PH);
#pragma unroll
        for (int f = 0; f < 4; ++f) {
            int cc = wn * 32 + f * 8 + 2 * t4;
            float e0 = __expf(sacc[f][0] - mx1), e1 = __expf(sacc[f][1] - mx1);
            float e2 = __expf(sacc[f][2] - mx2), e3 = __expf(sacc[f][3] - mx2);
            s1 += e0 + e1; s2 += e2 + e3;
            __half2 hp;
            hp.x = __float2half(e0); hp.y = __float2half(e1);
            *(__half2*)(PH + r1 * AP_STR + cc) = hp;
            hp.x = __float2half(e2); hp.y = __float2half(e3);
            *(__half2*)(PH + r2 * AP_STR + cc) = hp;
        }
        s1 += __shfl_xor_sync(0xffffffffu, s1, 1);
        s1 += __shfl_xor_sync(0xffffffffu, s1, 2);
        s2 += __shfl_xor_sync(0xffffffffu, s2, 1);
        s2 += __shfl_xor_sync(0xffffffffu, s2, 2);
        if (t4 == 0) { psum[wn * 64 + r1] = s1; psum[wn * 64 + r2] = s2; }
#pragma unroll
        for (int f = 0; f < 8; ++f) {
            oacc[f][0] *= fac1; oacc[f][1] *= fac1;
            oacc[f][2] *= fac2; oacc[f][3] *= fac2;
        }
        __syncthreads();                          // B3: PH + psum visible
        if (wn == 0 && t4 == 0) {
            lrow[r1] = lrow[r1] * fac1 + psum[r1] + psum[64 + r1];
            mrow[r1] = mx1;
            lrow[r2] = lrow[r2] * fac2 + psum[r2] + psum[64 + r2];
            mrow[r2] = mx2;
        }

#pragma unroll
        for (int ks = 0; ks < 4; ++ks) {
            uint32_t ph[4];
            LDSM4(ph, sb + AO_PH + poff + ks * 32);
#pragma unroll
            for (int g2 = 0; g2 < 4; ++g2) {
                uint32_t vh[4];
                uint32_t p = (uint32_t)((ks * 16 + vrow) * AQ_STR + wn * 64 + g2 * 16 + vc8) * 2;
                LDSM4T(vh, vb + p);
#pragma unroll
                for (int h = 0; h < 2; ++h)
                    mma_f16(oacc[g2 * 2 + h], ph, &vh[h * 2]);
            }
        }
        __syncthreads();                          // B4
    }

    {
        float i1 = 1.f / lrow[r1], i2 = 1.f / lrow[r2];
        int g1 = combined_row(fi, q0 + r1), g2r = combined_row(fi, q0 + r2);
#pragma unroll
        for (int f = 0; f < 8; ++f) {
            int col = coloff + wn * 64 + f * 8 + 2 * t4;
            __half2 p;
            p.x = __float2half(oacc[f][0] * i1); p.y = __float2half(oacc[f][1] * i1);
            *(__half2*)(OH + (size_t)g1 * C_DIM + col) = p;
            p.x = __float2half(oacc[f][2] * i2); p.y = __float2half(oacc[f][3] * i2);
            *(__half2*)(OH + (size_t)g2r * C_DIM + col) = p;
        }
    }
}

// ----------------------------------------------------------------- launch
extern "C" void kernel_launch(void* const* d_in, const int* in_sizes, int n_in,
                              void* d_out, int out_size)
{
    const float* temb  = (const float*)d_in[2];
    const float* cos_h = (const float*)d_in[3];
    const float* sin_h = (const float*)d_in[4];
    const float* cos_r = (const float*)d_in[5];
    const float* sin_r = (const float*)d_in[6];
    const float* l1lw = (const float*)d_in[7],  *l1lb = (const float*)d_in[8];
    const float* l1nw = (const float*)d_in[9],  *l1nb = (const float*)d_in[10];
    const float* l2lw = (const float*)d_in[11], *l2lb = (const float*)d_in[12];
    const float* l2nw = (const float*)d_in[13], *l2nb = (const float*)d_in[14];
    const float* wq = (const float*)d_in[15], *bq = (const float*)d_in[16];
    const float* wk = (const float*)d_in[17], *bk = (const float*)d_in[18];
    const float* wv = (const float*)d_in[19], *bv = (const float*)d_in[20];
    const float* nqw = (const float*)d_in[21], *nkw = (const float*)d_in[22];
    const float* wo = (const float*)d_in[23], *bo = (const float*)d_in[24];
    const float* fw1 = (const float*)d_in[25], *fb1 = (const float*)d_in[26];
    const float* fw2 = (const float*)d_in[27], *fb2 = (const float*)d_in[28];
    float* st = (float*)d_out;

    float *t1, *t2;
    __half *nrm, *qH, *kH, *vH, *aoH, *mid;
    __half *wqh, *wkh, *wvh, *woh, *f1h, *f2h;
    cudaGetSymbolAddress((void**)&t1,  g_t1);
    cudaGetSymbolAddress((void**)&t2,  g_t2);
    cudaGetSymbolAddress((void**)&nrm, g_nrm);
    cudaGetSymbolAddress((void**)&qH, g_qH);
    cudaGetSymbolAddress((void**)&kH, g_kH);
    cudaGetSymbolAddress((void**)&vH, g_vH);
    cudaGetSymbolAddress((void**)&aoH, g_aoH);
    cudaGetSymbolAddress((void**)&mid, g_mid);
    cudaGetSymbolAddress((void**)&wqh, g_wq);
    cudaGetSymbolAddress((void**)&wkh, g_wk);
    cudaGetSymbolAddress((void**)&wvh, g_wv);
    cudaGetSymbolAddress((void**)&woh, g_wo);
    cudaGetSymbolAddress((void**)&f1h, g_f1);
    cudaGetSymbolAddress((void**)&f2h, g_f2);

    cudaFuncSetAttribute(attn_kernel, cudaFuncAttributeMaxDynamicSharedMemorySize, ATTN_SMEM);
    cudaFuncSetAttribute(mma_gemm,    cudaFuncAttributeMaxDynamicSharedMemorySize, MG_SMEM);

    wconv_kernel<<<dim3(64, 64),   256>>>(wq,  wqh, C_DIM, C_DIM);
    wconv_kernel<<<dim3(64, 64),   256>>>(wk,  wkh, C_DIM, C_DIM);
    wconv_kernel<<<dim3(64, 64),   256>>>(wv,  wvh, C_DIM, C_DIM);
    wconv_kernel<<<dim3(64, 64),   256>>>(wo,  woh, C_DIM, C_DIM);
    wconv_kernel<<<dim3(256, 64),  256>>>(fw1, f1h, C_DIM, C_FFN);
    wconv_kernel<<<dim3(64, 256),  256>>>(fw2, f2h, C_FFN, C_DIM);

    temb_kernel<<<dim3(24, 2), 256>>>(temb, l1lw, l1lb, l2lw, l2lb, t1, t2);
    ln_mod_first<<<C_ROWS, 256>>>((const float*)d_in[0], (const float*)d_in[1],
                                  t1, l1nw, l1nb, nrm, st);
    mma_gemm<<<dim3(16, 36), 256, MG_SMEM>>>(nrm, wqh, bq, bq, 0, qH, C_DIM, C_DIM, 2);
    mma_gemm<<<dim3(16, 36), 256, MG_SMEM>>>(nrm, wkh, bk, bk, 0, kH, C_DIM, C_DIM, 2);
    mma_gemm<<<dim3(16, 36), 256, MG_SMEM>>>(nrm, wvh, bv, bv, 0, vH, C_DIM, C_DIM, 2);
    rmsrope_kernel<<<dim3(C_ROWS, 2), 256>>>(qH, kH, nqw, nkw, cos_h, sin_h, cos_r, sin_r);
    attn_kernel<<<dim3(18, 64), 256, ATTN_SMEM>>>(qH, kH, vH, aoH);
    mma_gemm<<<dim3(16, 36), 256, MG_SMEM>>>(aoH, woh, bo, t1 + 4096, st, 0, C_DIM, C_DIM, 3);
    ln_mod_kernel<<<C_ROWS, 256>>>(st, t2, l2nw, l2nb, nrm);
    mma_gemm<<<dim3(64, 36), 256, MG_SMEM>>>(nrm, f1h, fb1, fb1, 0, mid, C_FFN, C_DIM, 1);
    mma_gemm<<<dim3(16, 36), 256, MG_SMEM>>>(mid, f2h, fb2, t2 + 4096, st, 0, C_DIM, C_FFN, 3);
}